// round 8
// baseline (speedup 1.0000x reference)
#include <cuda_runtime.h>
#include <cstdint>
#include <math.h>

// ---------------------------------------------------------------------------
// PreferencePredictor (sm_100, mma.sync m16n8k16 fp16) — round 8
//
//   l      = llm @ Wl.T (+bl in epilogue)     [M,256]  GEMM, BM=128 BN=256
//   s_h    = dWs_h . acc + dbsP_h             -> a_h = sigmoid(s_h)
//   att    = base + sum_h a_h * c_h           [256]
//   logit  = relu(att)@Wo[:256] + relu(l)@Wo[256:] + bo
//
// vs R7: cooperative A->fp16 conversion (once per tile) + ldmatrix fragment
// loads; all preps fused into one 2-launch structure.
// ---------------------------------------------------------------------------

#define KTILES 24
#define ASTRIDE 40                          // floats per A row in fp32 stage
#define A_FLOATS (128*ASTRIDE)              // 5120
#define B_U32    4096                       // 16 kpairs x 256 n half2
#define STAGE_FLOATS (A_FLOATS + B_U32)     // 9216
#define NSTAGE 3
#define EPI_F (NSTAGE*STAGE_FLOATS)         // 27648

#define EPI_BASE 0
#define EPI_CC   256
#define EPI_WOA  1280
#define EPI_WOL  1536
#define EPI_BL   1792
#define EPI_DWS  2048
#define EPI_DBS  3072
#define EPI_RED  3080                        // [128][4][5]
#define EPI_AW   5640                        // [128][4]
#define EPI_PL   6152                        // [128]
#define EPI_RED2 6280                        // [128][2]
#define EPI_TOT  6536
#define HBUF_F   (EPI_F + EPI_TOT)           // 34184 (16B aligned: *4 = 136736)
#define SMEM_BYTES ((HBUF_F + 2048)*4)       // + 8KB half-A buffer

// ---- persistent scratch ----
__device__ __align__(256) float g_base[256], g_cc[4*256];
__device__ __align__(256) float g_dWs[4*256], g_dbsP[4];
__device__ __align__(256) uint32_t g_Wh[24*B_U32];  // half2-packed swizzled Wl

// ---- helpers ----
__device__ __forceinline__ uint32_t packh2(float lo, float hi){
    uint32_t r; asm("cvt.rn.f16x2.f32 %0, %1, %2;" : "=r"(r) : "f"(hi), "f"(lo)); return r;
}
__device__ __forceinline__ void cpa16(uint32_t dst, const void* src){
    asm volatile("cp.async.cg.shared.global [%0], [%1], 16;" :: "r"(dst), "l"(src));
}
__device__ __forceinline__ void cp_commit(){ asm volatile("cp.async.commit_group;" ::: "memory"); }
__device__ __forceinline__ void cp_wait2(){ asm volatile("cp.async.wait_group 2;" ::: "memory"); }

__device__ __forceinline__ void mma_f16(float&c0,float&c1,float&c2,float&c3,
                                        uint32_t a0,uint32_t a1,uint32_t a2,uint32_t a3,
                                        uint32_t b0,uint32_t b1){
    asm volatile(
        "mma.sync.aligned.m16n8k16.row.col.f32.f16.f16.f32 "
        "{%0,%1,%2,%3},{%4,%5,%6,%7},{%8,%9},{%0,%1,%2,%3};"
        : "+f"(c0),"+f"(c1),"+f"(c2),"+f"(c3)
        : "r"(a0),"r"(a1),"r"(a2),"r"(a3),"r"(b0),"r"(b1));
}
__device__ __forceinline__ void ldsm4(uint32_t* r, uint32_t addr){
    asm volatile("ldmatrix.sync.aligned.m8n8.x4.shared.b16 {%0,%1,%2,%3}, [%4];"
        : "=r"(r[0]),"=r"(r[1]),"=r"(r[2]),"=r"(r[3]) : "r"(addr));
}
__device__ __forceinline__ float wreduce(float s){
    #pragma unroll
    for (int o=16;o;o>>=1) s += __shfl_xor_sync(0xffffffffu, s, o);
    return s;
}

// ---- fused prep: block 0 = scalar chain; blocks 1..24 = Wl fp16 pack ----
__global__ void __launch_bounds__(256) prep_fused(
    const float* __restrict__ user, const float* __restrict__ query,
    const float* __restrict__ Wu, const float* __restrict__ bu,
    const float* __restrict__ Wq, const float* __restrict__ bq,
    const float* __restrict__ ipw, const float* __restrict__ ipb,
    const float* __restrict__ opw, const float* __restrict__ opb,
    const float* __restrict__ Wl, const float* __restrict__ bl){
    if (blockIdx.x > 0){
        // pack Wl tile kt into fragment-swizzled half2 layout
        int kt = blockIdx.x - 1;      // 0..23
        int n  = threadIdx.x;         // 0..255
        int qq = n & 7, ntg = n >> 3;
        uint32_t* dst = g_Wh + kt*B_U32;
        #pragma unroll
        for (int kp=0; kp<16; kp++){
            float lo = Wl[n*768 + kt*32 + kp*2];
            float hi = Wl[n*768 + kt*32 + kp*2 + 1];
            int s = (qq&1)*4 + (kp&3);
            int chunk = (ntg>>2) ^ s;
            dst[(kp*8+qq)*32 + chunk*4 + (ntg&3)] = packh2(lo, hi);
        }
        return;
    }
    // ---- chain (block 0) ----
    __shared__ float su[256], sqv[256], sk[512], sv[512], sWs[2048], sbs[8];
    __shared__ float sbuf[4][256];
    int tid = threadIdx.x, lane = tid&31, w = tid>>5;

    // phase 1: u, qv (512 dots of 768)
    for (int d=w; d<512; d+=8){
        const float *x, *W, *b; float* o; int i;
        if (d<256){ x=user;  W=Wu; b=bu; o=su;  i=d; }
        else      { x=query; W=Wq; b=bq; o=sqv; i=d-256; }
        float s=0.f;
        #pragma unroll
        for (int t=0;t<24;t++){ int jj=lane+t*32; s += x[jj]*W[i*768+jj]; }
        s = wreduce(s);
        if (!lane) o[i] = s + b[i];
    }
    __syncthreads();
    // phase 2: k, v (1024 dots of 256)
    for (int d=w; d<1024; d+=8){
        int i=d&255, which=d>>8, c=which&1, kv=which>>1;
        const float* ctx = c ? sqv : su;
        int row = 256 + kv*256 + i;
        float s=0.f;
        #pragma unroll
        for (int t=0;t<8;t++){ int jj=lane+t*32; s += ctx[jj]*ipw[row*256+jj]; }
        s = wreduce(s);
        if (!lane){ float val=s+ipb[row]; if (kv) sv[c*256+i]=val; else sk[c*256+i]=val; }
    }
    __syncthreads();
    // phase 3: base, cc, Ws, bs
    for (int d=w; d<3336; d+=8){
        float s=0.f;
        if (d<256){ int i=d;
            #pragma unroll
            for (int t=0;t<8;t++){ int jj=lane+t*32; s += sv[256+jj]*opw[i*256+jj]; }
            s = wreduce(s);
            if (!lane) g_base[i] = s + opb[i];
        } else if (d<1280){ int o=d-256, h=o>>8, i=o&255;
            #pragma unroll
            for (int t=0;t<2;t++){ int dd=lane+t*32; int jj=h*64+dd;
                s += (sv[jj]-sv[256+jj])*opw[i*256+jj]; }
            s = wreduce(s);
            if (!lane) g_cc[h*256+i] = s;
        } else if (d<3328){ int o=d-1280, r=o>>8, i=o&255, h=r>>1, kidx=r&1;
            #pragma unroll
            for (int t=0;t<2;t++){ int dd=lane+t*32;
                s += sk[kidx*256+h*64+dd]*ipw[(h*64+dd)*256+i]; }
            s = wreduce(s);
            if (!lane) sWs[r*256+i] = 0.125f*s;
        } else { int r=d-3328, h=r>>1, kidx=r&1;
            #pragma unroll
            for (int t=0;t<2;t++){ int dd=lane+t*32;
                s += ipb[h*64+dd]*sk[kidx*256+h*64+dd]; }
            s = wreduce(s);
            if (!lane) sbs[r] = 0.125f*s;
        }
    }
    __syncthreads();
    // phase 4: dWs, dbsP
    {
        int i = tid;
        float blv = bl[i];
        #pragma unroll
        for (int h=0;h<4;h++){
            float dv = sWs[2*h*256+i] - sWs[(2*h+1)*256+i];
            g_dWs[h*256+i] = dv;
            sbuf[h][i] = dv*blv;
        }
    }
    __syncthreads();
    if (tid < 4){
        float s = sbs[2*tid] - sbs[2*tid+1];
        for (int t=0;t<256;t++) s += sbuf[tid][t];
        g_dbsP[tid] = s;
    }
}

// ---- main GEMM + fused epilogue ----
__global__ void __launch_bounds__(256,1) main_gemm(
    const float* __restrict__ llm, const float* __restrict__ Wo,
    const float* __restrict__ bo, const float* __restrict__ bl,
    float* __restrict__ out){
    extern __shared__ float sm[];
    const int tid = threadIdx.x, lane = tid&31, warp = tid>>5;
    const int j = lane&3, qq = lane>>2;
    const int wm = warp&1, wn = warp>>1;           // 2 x 4 warp grid
    const uint32_t smu = (uint32_t)__cvta_generic_to_shared(sm);
    float* epi = sm + EPI_F;
    uint32_t* hb = (uint32_t*)(sm + HBUF_F);
    const uint32_t hb_u = smu + (uint32_t)HBUF_F*4u;

    auto issue = [&](int kt){
        int slot = kt % NSTAGE;
        uint32_t sb = smu + (uint32_t)(slot*STAGE_FLOATS)*4u;
        const float* Asrc = llm + (size_t)blockIdx.x*(128*768) + kt*32;
        #pragma unroll
        for (int ch=tid; ch<1024; ch+=256){
            int row = ch>>3, u = ch&7;
            cpa16(sb + (uint32_t)(row*ASTRIDE + u*4)*4u, Asrc + (size_t)row*768 + u*4);
        }
        const uint32_t* Bsrc = g_Wh + kt*B_U32;
        uint32_t bb = sb + (uint32_t)A_FLOATS*4u;
        #pragma unroll
        for (int ch=tid; ch<1024; ch+=256)
            cpa16(bb + (uint32_t)ch*16u, Bsrc + ch*4);
    };

    issue(0); cp_commit();
    issue(1); cp_commit();

    // stage epilogue constants (overlaps async loads)
    {
        int i = tid;
        epi[EPI_BASE+i] = g_base[i];
        #pragma unroll
        for (int h=0;h<4;h++) epi[EPI_CC + h*256 + i] = g_cc[h*256+i];
        epi[EPI_WOA+i] = __ldg(Wo+i);
        epi[EPI_WOL+i] = __ldg(Wo+256+i);
        epi[EPI_BL +i] = __ldg(bl+i);
        #pragma unroll
        for (int h=0;h<4;h++) epi[EPI_DWS + h*256 + i] = g_dWs[h*256+i];
        if (i<4) epi[EPI_DBS+i] = g_dbsP[i];
    }

    float acc[4][8][4];
    #pragma unroll
    for (int t=0;t<4;t++)
        #pragma unroll
        for (int nt=0;nt<8;nt++)
            #pragma unroll
            for (int c=0;c<4;c++) acc[t][nt][c]=0.f;

    const int bsw = (qq&1)*4 + j;          // B chunk swizzle key
    // ldmatrix per-lane address components (row within tile, kc chunk)
    const int lrow = (lane&7) + ((lane>>3)&1)*8;   // 0..15
    const int lkc  = lane>>4;                       // 0..1

    for (int kt=0; kt<KTILES; kt++){
        if (kt+2 < KTILES) issue(kt+2);
        cp_commit();
        cp_wait2();
        __syncthreads();

        const int slot = kt % NSTAGE;
        const float* As = sm + slot*STAGE_FLOATS;
        const uint32_t* Bs = (const uint32_t*)(As + A_FLOATS);

        // cooperative A fp32 -> fp16 conversion: hbuf[kc][row] 16B chunks
        #pragma unroll
        for (int i=0;i<2;i++){
            int c2 = tid + i*256;            // 0..511
            int kc = c2>>7, row = c2&127;
            const float4* src = (const float4*)(As + row*ASTRIDE + kc*8);
            float4 v0 = src[0], v1 = src[1];
            uint4 hv;
            hv.x = packh2(v0.x, v0.y); hv.y = packh2(v0.z, v0.w);
            hv.z = packh2(v1.x, v1.y); hv.w = packh2(v1.z, v1.w);
            *(uint4*)(hb + c2*4) = hv;
        }
        __syncthreads();

        #pragma unroll
        for (int ks=0; ks<2; ks++){
            // B fragments: 4 x LDS.128
            uint32_t bf[2][8];
            #pragma unroll
            for (int r=0;r<2;r++){
                const int kp = ks*8 + j + r*4;
                const uint32_t* cell = Bs + (kp*8+qq)*32;
                #pragma unroll
                for (int c=0;c<2;c++){
                    const int chunk = (wn*2 + c) ^ bsw;
                    const uint4 v = *(const uint4*)(cell + chunk*4);
                    bf[r][c*4+0]=v.x; bf[r][c*4+1]=v.y; bf[r][c*4+2]=v.z; bf[r][c*4+3]=v.w;
                }
            }
            // A fragments: 4 x ldmatrix.x4
            uint32_t af[4][4];
            const uint32_t abase = hb_u +
                (uint32_t)(((ks*2 + lkc)*128 + wm*64 + lrow)*16);
            #pragma unroll
            for (int t=0;t<4;t++)
                ldsm4(af[t], abase + (uint32_t)t*256u);
            #pragma unroll
            for (int t=0;t<4;t++)
                #pragma unroll
                for (int nt=0;nt<8;nt++)
                    mma_f16(acc[t][nt][0],acc[t][nt][1],acc[t][nt][2],acc[t][nt][3],
                            af[t][0],af[t][1],af[t][2],af[t][3],
                            bf[0][nt], bf[1][nt]);
        }
        __syncthreads();
    }

    // ---- epilogue phase A: per-thread partials over owned cols ----
    float pl[4][2];
    float sh[4][2][4];
    #pragma unroll
    for (int t=0;t<4;t++)
        #pragma unroll
        for (int hf=0;hf<2;hf++){
            pl[t][hf]=0.f;
            #pragma unroll
            for (int h=0;h<4;h++) sh[t][hf][h]=0.f;
        }
    #pragma unroll
    for (int nt=0;nt<8;nt++){
        #pragma unroll
        for (int cb=0;cb<2;cb++){
            const int col = wn*64 + nt*8 + 2*j + cb;
            const float blv = epi[EPI_BL+col];
            const float wol = epi[EPI_WOL+col];
            const float w0 = epi[EPI_DWS+col];
            const float w1 = epi[EPI_DWS+256+col];
            const float w2 = epi[EPI_DWS+512+col];
            const float w3 = epi[EPI_DWS+768+col];
            #pragma unroll
            for (int t=0;t<4;t++)
                #pragma unroll
                for (int hf=0;hf<2;hf++){
                    float av = acc[t][nt][hf*2+cb];
                    pl[t][hf] += fmaxf(av+blv,0.f)*wol;
                    sh[t][hf][0] += w0*av;
                    sh[t][hf][1] += w1*av;
                    sh[t][hf][2] += w2*av;
                    sh[t][hf][3] += w3*av;
                }
        }
    }
    #pragma unroll
    for (int t=0;t<4;t++)
        #pragma unroll
        for (int hf=0;hf<2;hf++){
            float v4 = pl[t][hf];
            v4 += __shfl_xor_sync(0xffffffffu, v4, 1);
            v4 += __shfl_xor_sync(0xffffffffu, v4, 2);
            float vh[4];
            #pragma unroll
            for (int h=0;h<4;h++){
                float v = sh[t][hf][h];
                v += __shfl_xor_sync(0xffffffffu, v, 1);
                v += __shfl_xor_sync(0xffffffffu, v, 2);
                vh[h]=v;
            }
            if (j==0){
                int row = wm*64 + t*16 + qq + hf*8;
                float* rp = epi + EPI_RED + (row*4+wn)*5;
                rp[0]=vh[0]; rp[1]=vh[1]; rp[2]=vh[2]; rp[3]=vh[3]; rp[4]=v4;
            }
        }
    __syncthreads();

    // ---- phase B: per-row scores + sigmoid ----
    if (tid < 128){
        int row = tid;
        float s0=epi[EPI_DBS+0], s1=epi[EPI_DBS+1], s2=epi[EPI_DBS+2], s3=epi[EPI_DBS+3];
        float p=0.f;
        #pragma unroll
        for (int w=0;w<4;w++){
            float* rp = epi + EPI_RED + (row*4+w)*5;
            s0+=rp[0]; s1+=rp[1]; s2+=rp[2]; s3+=rp[3]; p+=rp[4];
        }
        epi[EPI_AW+row*4+0] = 1.f/(1.f+expf(-s0));
        epi[EPI_AW+row*4+1] = 1.f/(1.f+expf(-s1));
        epi[EPI_AW+row*4+2] = 1.f/(1.f+expf(-s2));
        epi[EPI_AW+row*4+3] = 1.f/(1.f+expf(-s3));
        epi[EPI_PL+row] = p;
    }
    __syncthreads();

    // ---- phase C: attention dot, 2 threads per row ----
    {
        int row = tid & 127, hf = tid >> 7;
        float a0=epi[EPI_AW+row*4+0], a1=epi[EPI_AW+row*4+1],
              a2=epi[EPI_AW+row*4+2], a3=epi[EPI_AW+row*4+3];
        float p2=0.f;
        #pragma unroll 8
        for (int d=hf*128; d<hf*128+128; d++){
            float att = epi[EPI_BASE+d] + a0*epi[EPI_CC+d] + a1*epi[EPI_CC+256+d]
                      + a2*epi[EPI_CC+512+d] + a3*epi[EPI_CC+768+d];
            p2 += fmaxf(att,0.f)*epi[EPI_WOA+d];
        }
        epi[EPI_RED2 + row*2 + hf] = p2;
    }
    __syncthreads();

    if (tid < 128){
        out[blockIdx.x*128 + tid] = epi[EPI_PL+tid] + epi[EPI_RED2+tid*2]
                                  + epi[EPI_RED2+tid*2+1] + __ldg(bo);
    }
}

// ---------------------------------------------------------------------------
extern "C" void kernel_launch(void* const* d_in, const int* in_sizes, int n_in,
                              void* d_out, int out_size){
    const float* user  = (const float*)d_in[0];
    const float* query = (const float*)d_in[1];
    const float* llm   = (const float*)d_in[2];
    const float* Wu    = (const float*)d_in[3];
    const float* bu    = (const float*)d_in[4];
    const float* Wq    = (const float*)d_in[5];
    const float* bq    = (const float*)d_in[6];
    const float* Wl    = (const float*)d_in[7];
    const float* bl    = (const float*)d_in[8];
    const float* ipw   = (const float*)d_in[9];
    const float* ipb   = (const float*)d_in[10];
    const float* opw   = (const float*)d_in[11];
    const float* opb   = (const float*)d_in[12];
    const float* Wo    = (const float*)d_in[13];
    const float* bo    = (const float*)d_in[14];
    float* out = (float*)d_out;

    int M = in_sizes[2] / 768;

    cudaFuncSetAttribute(main_gemm, cudaFuncAttributeMaxDynamicSharedMemorySize, SMEM_BYTES);

    prep_fused<<<25, 256>>>(user, query, Wu, bu, Wq, bq,
                            ipw, ipb, opw, opb, Wl, bl);
    main_gemm <<<M/128, 256, SMEM_BYTES>>>(llm, Wo, bo, bl, out);
}

// round 12
// speedup vs baseline: 2.4912x; 2.4912x over previous
#include <cuda_runtime.h>
#include <cstdint>
#include <math.h>

// ---------------------------------------------------------------------------
// PreferencePredictor (sm_100, mma.sync m16n8k16 fp16) — round 11
// (resubmit of R9/R10; both benches were infra failures, kernel never ran)
//
//   l      = llm @ Wl.T (+bl in epilogue)     [M,256]  GEMM, BM=128 BN=256
//   s_h    = dWs_h . acc + dbsP_h             -> a_h = sigmoid(s_h)
//   att    = base + sum_h a_h * c_h           [256]
//   logit  = relu(att)@Wo[:256] + relu(l)@Wo[256:] + bo
//
// vs R7: 512 threads (4x4 warp grid, 4 warps/SMSP), 1 barrier per k-tile.
// vs R8: parallel preps restored (R8's serial prep block cost ~370us).
// ---------------------------------------------------------------------------

#define KTILES 24
#define ASTRIDE 40                          // floats per A row (conflict-free LDS.64)
#define A_FLOATS (128*ASTRIDE)              // 5120
#define B_U32    4096                       // 16 kpairs x 256 n half2
#define STAGE_FLOATS (A_FLOATS + B_U32)     // 9216
#define NSTAGE 3
#define EPI_F (NSTAGE*STAGE_FLOATS)         // 27648

#define EPI_BASE 0
#define EPI_CC   256
#define EPI_WOA  1280
#define EPI_WOL  1536
#define EPI_BL   1792
#define EPI_DWS  2048
#define EPI_DBS  3072
#define EPI_RED  3080                        // [128][4][5]
#define EPI_AW   5640                        // [128][4]
#define EPI_PL   6152                        // [128]
#define EPI_RED2 6280                        // [128][4]
#define EPI_TOT  6792
#define SMEM_BYTES ((EPI_F + EPI_TOT)*4)

// ---- persistent scratch ----
__device__ __align__(256) float g_u[256], g_qv[256];
__device__ __align__(256) float g_k[512], g_v[512];
__device__ __align__(256) float g_Ws[8*256], g_bs[8];
__device__ __align__(256) float g_base[256], g_cc[4*256];
__device__ __align__(256) float g_dWs[4*256], g_dbsP[4];
__device__ __align__(256) uint32_t g_Wh[24*B_U32];  // half2-packed swizzled Wl

// ---- helpers ----
__device__ __forceinline__ uint32_t packh2(float lo, float hi){
    uint32_t r; asm("cvt.rn.f16x2.f32 %0, %1, %2;" : "=r"(r) : "f"(hi), "f"(lo)); return r;
}
__device__ __forceinline__ void cpa16(uint32_t dst, const void* src){
    asm volatile("cp.async.cg.shared.global [%0], [%1], 16;" :: "r"(dst), "l"(src));
}
__device__ __forceinline__ void cp_commit(){ asm volatile("cp.async.commit_group;" ::: "memory"); }
__device__ __forceinline__ void cp_wait1(){ asm volatile("cp.async.wait_group 1;" ::: "memory"); }

__device__ __forceinline__ void mma_f16(float&c0,float&c1,float&c2,float&c3,
                                        uint32_t a0,uint32_t a1,uint32_t a2,uint32_t a3,
                                        uint32_t b0,uint32_t b1){
    asm volatile(
        "mma.sync.aligned.m16n8k16.row.col.f32.f16.f16.f32 "
        "{%0,%1,%2,%3},{%4,%5,%6,%7},{%8,%9},{%0,%1,%2,%3};"
        : "+f"(c0),"+f"(c1),"+f"(c2),"+f"(c3)
        : "r"(a0),"r"(a1),"r"(a2),"r"(a3),"r"(b0),"r"(b1));
}
__device__ __forceinline__ float wreduce(float s){
    #pragma unroll
    for (int o=16;o;o>>=1) s += __shfl_xor_sync(0xffffffffu, s, o);
    return s;
}

// ---- prep 1: u, qv ----
__global__ void __launch_bounds__(256) prep_uq(
    const float* __restrict__ user, const float* __restrict__ query,
    const float* __restrict__ Wu, const float* __restrict__ bu,
    const float* __restrict__ Wq, const float* __restrict__ bq){
    int w = blockIdx.x*8 + (threadIdx.x>>5);
    int lane = threadIdx.x&31;
    const float *x, *W, *b; float* out; int i;
    if (w < 256){ x=user;  W=Wu; b=bu; out=g_u;  i=w; }
    else        { x=query; W=Wq; b=bq; out=g_qv; i=w-256; }
    float s=0.f;
    #pragma unroll
    for (int t=0;t<24;t++){ int jj=lane+t*32; s += x[jj]*W[i*768+jj]; }
    s = wreduce(s);
    if (!lane) out[i] = s + b[i];
}

// ---- prep 2: k, v ----
__global__ void __launch_bounds__(256) prep_kv(
    const float* __restrict__ ipw, const float* __restrict__ ipb){
    int w = blockIdx.x*8 + (threadIdx.x>>5);   // 0..1023
    int lane = threadIdx.x&31;
    int i = w & 255;
    int which = w >> 8;
    int c = which & 1;
    int kv = which >> 1;
    const float* ctx = c ? g_qv : g_u;
    int row = 256 + kv*256 + i;
    float s=0.f;
    #pragma unroll
    for (int t=0;t<8;t++){ int jj=lane+t*32; s += ctx[jj]*ipw[row*256+jj]; }
    s = wreduce(s);
    if (!lane){
        float val = s + ipb[row];
        if (kv) g_v[c*256+i] = val; else g_k[c*256+i] = val;
    }
}

// ---- prep 3: W_s, b_s, base, c ----
__global__ void __launch_bounds__(256) prep_small(
    const float* __restrict__ ipw, const float* __restrict__ ipb,
    const float* __restrict__ opw, const float* __restrict__ opb){
    int w = blockIdx.x*8 + (threadIdx.x>>5);
    int lane = threadIdx.x&31;
    float s=0.f;
    if (w < 256){
        int i=w;
        #pragma unroll
        for (int t=0;t<8;t++){ int jj=lane+t*32; s += g_v[256+jj]*opw[i*256+jj]; }
        s = wreduce(s);
        if (!lane) g_base[i] = s + opb[i];
    } else if (w < 1280){
        int o=w-256, h=o>>8, i=o&255;
        #pragma unroll
        for (int t=0;t<2;t++){ int d=lane+t*32; int jj=h*64+d;
            s += (g_v[jj]-g_v[256+jj])*opw[i*256+jj]; }
        s = wreduce(s);
        if (!lane) g_cc[h*256+i] = s;
    } else if (w < 3328){
        int o=w-1280, r=o>>8, i=o&255, h=r>>1, kidx=r&1;
        #pragma unroll
        for (int t=0;t<2;t++){ int d=lane+t*32;
            s += g_k[kidx*256+h*64+d]*ipw[(h*64+d)*256+i]; }
        s = wreduce(s);
        if (!lane) g_Ws[r*256+i] = 0.125f*s;
    } else if (w < 3336){
        int r=w-3328, h=r>>1, kidx=r&1;
        #pragma unroll
        for (int t=0;t<2;t++){ int d=lane+t*32;
            s += ipb[h*64+d]*g_k[kidx*256+h*64+d]; }
        s = wreduce(s);
        if (!lane) g_bs[r] = 0.125f*s;
    }
}

// ---- prep 4: dWs, dbsP ----
__global__ void __launch_bounds__(256) prep_const(const float* __restrict__ bl){
    __shared__ float sbuf[4][256];
    int i = threadIdx.x;
    float blv = bl[i];
    #pragma unroll
    for (int h=0;h<4;h++){
        float d = g_Ws[(2*h)*256+i] - g_Ws[(2*h+1)*256+i];
        g_dWs[h*256+i] = d;
        sbuf[h][i] = d * blv;
    }
    __syncthreads();
    if (i < 4){
        float s = g_bs[2*i] - g_bs[2*i+1];
        for (int t=0;t<256;t++) s += sbuf[i][t];
        g_dbsP[i] = s;
    }
}

// ---- prep 5: fp16-packed, fragment-swizzled weights ----
__global__ void __launch_bounds__(256) prep_Bh(const float* __restrict__ Wl){
    int kt = blockIdx.x;          // 0..23
    int n  = threadIdx.x;         // 0..255
    int qq = n & 7, ntg = n >> 3;
    uint32_t* dst = g_Wh + kt*B_U32;
    #pragma unroll
    for (int kp=0; kp<16; kp++){
        float lo = Wl[n*768 + kt*32 + kp*2];
        float hi = Wl[n*768 + kt*32 + kp*2 + 1];
        int s = (qq&1)*4 + (kp&3);
        int chunk = (ntg>>2) ^ s;
        dst[(kp*8+qq)*32 + chunk*4 + (ntg&3)] = packh2(lo, hi);
    }
}

// ---- main GEMM + fused epilogue: 512 threads, 4x4 warp grid ----
__global__ void __launch_bounds__(512,1) main_gemm(
    const float* __restrict__ llm, const float* __restrict__ Wo,
    const float* __restrict__ bo, const float* __restrict__ bl,
    float* __restrict__ out){
    extern __shared__ float sm[];
    const int tid = threadIdx.x, lane = tid&31, warp = tid>>5;   // warp 0..15
    const int j = lane&3, qq = lane>>2;
    const int wm = warp&3, wn = warp>>2;           // 4 x 4 warp grid
    const uint32_t smu = (uint32_t)__cvta_generic_to_shared(sm);
    float* epi = sm + EPI_F;

    auto issue = [&](int kt){
        int slot = kt % NSTAGE;
        uint32_t sb = smu + (uint32_t)(slot*STAGE_FLOATS)*4u;
        const float* Asrc = llm + (size_t)blockIdx.x*(128*768) + kt*32;
        #pragma unroll
        for (int ch=tid; ch<1024; ch+=512){
            int row = ch>>3, u = ch&7;
            cpa16(sb + (uint32_t)(row*ASTRIDE + u*4)*4u, Asrc + (size_t)row*768 + u*4);
        }
        const uint32_t* Bsrc = g_Wh + kt*B_U32;
        uint32_t bb = sb + (uint32_t)A_FLOATS*4u;
        #pragma unroll
        for (int ch=tid; ch<1024; ch+=512)
            cpa16(bb + (uint32_t)ch*16u, Bsrc + ch*4);
    };

    issue(0); cp_commit();
    issue(1); cp_commit();

    // stage epilogue constants (overlaps async loads)
    if (tid < 256){
        int i = tid;
        epi[EPI_BASE+i] = g_base[i];
        #pragma unroll
        for (int h=0;h<4;h++) epi[EPI_CC + h*256 + i] = g_cc[h*256+i];
        epi[EPI_WOA+i] = __ldg(Wo+i);
        epi[EPI_WOL+i] = __ldg(Wo+256+i);
        epi[EPI_BL +i] = __ldg(bl+i);
        #pragma unroll
        for (int h=0;h<4;h++) epi[EPI_DWS + h*256 + i] = g_dWs[h*256+i];
        if (i<4) epi[EPI_DBS+i] = g_dbsP[i];
    }

    float acc[2][8][4];
    #pragma unroll
    for (int t=0;t<2;t++)
        #pragma unroll
        for (int nt=0;nt<8;nt++)
            #pragma unroll
            for (int c=0;c<4;c++) acc[t][nt][c]=0.f;

    const int bsw = (qq&1)*4 + j;          // B chunk swizzle key

    for (int kt=0; kt<KTILES; kt++){
        cp_wait1();              // tile kt resident (kt+1 still in flight)
        __syncthreads();
        if (kt+2 < KTILES) issue(kt+2);
        cp_commit();

        const int slot = kt % NSTAGE;
        const float* As = sm + slot*STAGE_FLOATS;
        const uint32_t* Bs = (const uint32_t*)(As + A_FLOATS);

        #pragma unroll
        for (int ks=0; ks<2; ks++){
            // B fragments: 4 x LDS.128
            uint32_t bf[2][8];
            #pragma unroll
            for (int r=0;r<2;r++){
                const int kp = ks*8 + j + r*4;
                const uint32_t* cell = Bs + (kp*8+qq)*32;
                #pragma unroll
                for (int c=0;c<2;c++){
                    const int chunk = (wn*2 + c) ^ bsw;
                    const uint4 v = *(const uint4*)(cell + chunk*4);
                    bf[r][c*4+0]=v.x; bf[r][c*4+1]=v.y; bf[r][c*4+2]=v.z; bf[r][c*4+3]=v.w;
                }
            }
            // A fragments: 8 x LDS.64 + cvt (m32 per warp)
            uint32_t af[2][4];
            const int k0 = ks*16 + 2*j;
            #pragma unroll
            for (int t=0;t<2;t++){
                const int row = wm*32 + t*16 + qq;
                float2 p0 = *(const float2*)(As + row*ASTRIDE + k0);
                float2 p1 = *(const float2*)(As + (row+8)*ASTRIDE + k0);
                float2 p2 = *(const float2*)(As + row*ASTRIDE + k0 + 8);
                float2 p3 = *(const float2*)(As + (row+8)*ASTRIDE + k0 + 8);
                af[t][0] = packh2(p0.x, p0.y);
                af[t][1] = packh2(p1.x, p1.y);
                af[t][2] = packh2(p2.x, p2.y);
                af[t][3] = packh2(p3.x, p3.y);
            }
            #pragma unroll
            for (int t=0;t<2;t++)
                #pragma unroll
                for (int nt=0;nt<8;nt++)
                    mma_f16(acc[t][nt][0],acc[t][nt][1],acc[t][nt][2],acc[t][nt][3],
                            af[t][0],af[t][1],af[t][2],af[t][3],
                            bf[0][nt], bf[1][nt]);
        }
    }
    __syncthreads();

    // ---- epilogue phase A: per-thread partials over owned cols ----
    float pl[2][2];
    float sh[2][2][4];
    #pragma unroll
    for (int t=0;t<2;t++)
        #pragma unroll
        for (int hf=0;hf<2;hf++){
            pl[t][hf]=0.f;
            #pragma unroll
            for (int h=0;h<4;h++) sh[t][hf][h]=0.f;
        }
    #pragma unroll
    for (int nt=0;nt<8;nt++){
        #pragma unroll
        for (int cb=0;cb<2;cb++){
            const int col = wn*64 + nt*8 + 2*j + cb;
            const float blv = epi[EPI_BL+col];
            const float wol = epi[EPI_WOL+col];
            const float w0 = epi[EPI_DWS+col];
            const float w1 = epi[EPI_DWS+256+col];
            const float w2 = epi[EPI_DWS+512+col];
            const float w3 = epi[EPI_DWS+768+col];
            #pragma unroll
            for (int t=0;t<2;t++)
                #pragma unroll
                for (int hf=0;hf<2;hf++){
                    float av = acc[t][nt][hf*2+cb];
                    pl[t][hf] += fmaxf(av+blv,0.f)*wol;
                    sh[t][hf][0] += w0*av;
                    sh[t][hf][1] += w1*av;
                    sh[t][hf][2] += w2*av;
                    sh[t][hf][3] += w3*av;
                }
        }
    }
    #pragma unroll
    for (int t=0;t<2;t++)
        #pragma unroll
        for (int hf=0;hf<2;hf++){
            float v4 = pl[t][hf];
            v4 += __shfl_xor_sync(0xffffffffu, v4, 1);
            v4 += __shfl_xor_sync(0xffffffffu, v4, 2);
            float vh[4];
            #pragma unroll
            for (int h=0;h<4;h++){
                float v = sh[t][hf][h];
                v += __shfl_xor_sync(0xffffffffu, v, 1);
                v += __shfl_xor_sync(0xffffffffu, v, 2);
                vh[h]=v;
            }
            if (j==0){
                int row = wm*32 + t*16 + qq + hf*8;
                float* rp = epi + EPI_RED + (row*4+wn)*5;
                rp[0]=vh[0]; rp[1]=vh[1]; rp[2]=vh[2]; rp[3]=vh[3]; rp[4]=v4;
            }
        }
    __syncthreads();

    // ---- phase B: per-row scores + sigmoid ----
    if (tid < 128){
        int row = tid;
        float s0=epi[EPI_DBS+0], s1=epi[EPI_DBS+1], s2=epi[EPI_DBS+2], s3=epi[EPI_DBS+3];
        float p=0.f;
        #pragma unroll
        for (int w=0;w<4;w++){
            float* rp = epi + EPI_RED + (row*4+w)*5;
            s0+=rp[0]; s1+=rp[1]; s2+=rp[2]; s3+=rp[3]; p+=rp[4];
        }
        epi[EPI_AW+row*4+0] = 1.f/(1.f+expf(-s0));
        epi[EPI_AW+row*4+1] = 1.f/(1.f+expf(-s1));
        epi[EPI_AW+row*4+2] = 1.f/(1.f+expf(-s2));
        epi[EPI_AW+row*4+3] = 1.f/(1.f+expf(-s3));
        epi[EPI_PL+row] = p;
    }
    __syncthreads();

    // ---- phase C: attention dot, 4 threads per row ----
    {
        int row = tid & 127, hf = tid >> 7;     // hf 0..3
        float a0=epi[EPI_AW+row*4+0], a1=epi[EPI_AW+row*4+1],
              a2=epi[EPI_AW+row*4+2], a3=epi[EPI_AW+row*4+3];
        float p2=0.f;
        #pragma unroll 8
        for (int d=hf*64; d<hf*64+64; d++){
            float att = epi[EPI_BASE+d] + a0*epi[EPI_CC+d] + a1*epi[EPI_CC+256+d]
                      + a2*epi[EPI_CC+512+d] + a3*epi[EPI_CC+768+d];
            p2 += fmaxf(att,0.f)*epi[EPI_WOA+d];
        }
        epi[EPI_RED2 + row*4 + hf] = p2;
    }
    __syncthreads();

    if (tid < 128){
        out[blockIdx.x*128 + tid] = epi[EPI_PL+tid]
            + epi[EPI_RED2+tid*4] + epi[EPI_RED2+tid*4+1]
            + epi[EPI_RED2+tid*4+2] + epi[EPI_RED2+tid*4+3] + __ldg(bo);
    }
}

// ---------------------------------------------------------------------------
extern "C" void kernel_launch(void* const* d_in, const int* in_sizes, int n_in,
                              void* d_out, int out_size){
    const float* user  = (const float*)d_in[0];
    const float* query = (const float*)d_in[1];
    const float* llm   = (const float*)d_in[2];
    const float* Wu    = (const float*)d_in[3];
    const float* bu    = (const float*)d_in[4];
    const float* Wq    = (const float*)d_in[5];
    const float* bq    = (const float*)d_in[6];
    const float* Wl    = (const float*)d_in[7];
    const float* bl    = (const float*)d_in[8];
    const float* ipw   = (const float*)d_in[9];
    const float* ipb   = (const float*)d_in[10];
    const float* opw   = (const float*)d_in[11];
    const float* opb   = (const float*)d_in[12];
    const float* Wo    = (const float*)d_in[13];
    const float* bo    = (const float*)d_in[14];
    float* out = (float*)d_out;

    int M = in_sizes[2] / 768;

    cudaFuncSetAttribute(main_gemm, cudaFuncAttributeMaxDynamicSharedMemorySize, SMEM_BYTES);

    prep_uq   <<<64, 256>>>(user, query, Wu, bu, Wq, bq);
    prep_kv   <<<128,256>>>(ipw, ipb);
    prep_small<<<417,256>>>(ipw, ipb, opw, opb);
    prep_const<<<1,  256>>>(bl);
    prep_Bh   <<<24, 256>>>(Wl);
    main_gemm <<<M/128, 512, SMEM_BYTES>>>(llm, Wo, bo, bl, out);
}

// round 13
// speedup vs baseline: 2.6000x; 1.0437x over previous
#include <cuda_runtime.h>
#include <cstdint>
#include <math.h>

// ---------------------------------------------------------------------------
// PreferencePredictor (sm_100, mma.sync m16n8k16 fp16) — round 13
//
//   l      = llm @ Wl.T (+bl in epilogue)     [M,256]  GEMM, BM=128 BN=256
//   s_h    = dbs_h + dWs_h . (acc+bl)         -> a_h = sigmoid(s_h)
//   att    = base + sum_h a_h * c_h           [256]
//   logit  = relu(att)@Wo[:256] + relu(l)@Wo[256:] + bo
//
// vs R7 (best, 241.7us): prep_const folded into epilogue (dWs/dbs formed
// inline; score accumulated over lv=acc+bl), prep_small+prep_Bh merged.
// Main loop byte-equivalent to R7's (measured-best config).
// ---------------------------------------------------------------------------

#define KTILES 24
#define ASTRIDE 40                          // floats per A row (conflict-free LDS.64)
#define A_FLOATS (128*ASTRIDE)              // 5120
#define B_U32    4096                       // 16 kpairs x 256 n half2
#define STAGE_FLOATS (A_FLOATS + B_U32)     // 9216
#define NSTAGE 3
#define EPI_F (NSTAGE*STAGE_FLOATS)         // 27648

#define EPI_BASE 0
#define EPI_CC   256
#define EPI_WOA  1280
#define EPI_WOL  1536
#define EPI_BL   1792
#define EPI_DWS  2048
#define EPI_DBS  3072
#define EPI_RED  3080                        // [128][4][5]
#define EPI_AW   5640                        // [128][4]
#define EPI_PL   6152                        // [128]
#define EPI_RED2 6280                        // [128][2]
#define EPI_TOT  6536
#define SMEM_BYTES ((EPI_F + EPI_TOT)*4)

// ---- persistent scratch ----
__device__ __align__(256) float g_u[256], g_qv[256];
__device__ __align__(256) float g_k[512], g_v[512];
__device__ __align__(256) float g_Ws[8*256], g_bs[8];
__device__ __align__(256) float g_base[256], g_cc[4*256];
__device__ __align__(256) uint32_t g_Wh[24*B_U32];  // half2-packed swizzled Wl

// ---- helpers ----
__device__ __forceinline__ uint32_t packh2(float lo, float hi){
    uint32_t r; asm("cvt.rn.f16x2.f32 %0, %1, %2;" : "=r"(r) : "f"(hi), "f"(lo)); return r;
}
__device__ __forceinline__ void cpa16(uint32_t dst, const void* src){
    asm volatile("cp.async.cg.shared.global [%0], [%1], 16;" :: "r"(dst), "l"(src));
}
__device__ __forceinline__ void cp_commit(){ asm volatile("cp.async.commit_group;" ::: "memory"); }
__device__ __forceinline__ void cp_wait2(){ asm volatile("cp.async.wait_group 2;" ::: "memory"); }

__device__ __forceinline__ void mma_f16(float&c0,float&c1,float&c2,float&c3,
                                        uint32_t a0,uint32_t a1,uint32_t a2,uint32_t a3,
                                        uint32_t b0,uint32_t b1){
    asm volatile(
        "mma.sync.aligned.m16n8k16.row.col.f32.f16.f16.f32 "
        "{%0,%1,%2,%3},{%4,%5,%6,%7},{%8,%9},{%0,%1,%2,%3};"
        : "+f"(c0),"+f"(c1),"+f"(c2),"+f"(c3)
        : "r"(a0),"r"(a1),"r"(a2),"r"(a3),"r"(b0),"r"(b1));
}
__device__ __forceinline__ float wreduce(float s){
    #pragma unroll
    for (int o=16;o;o>>=1) s += __shfl_xor_sync(0xffffffffu, s, o);
    return s;
}

// ---- prep 1: u, qv ----
__global__ void __launch_bounds__(256) prep_uq(
    const float* __restrict__ user, const float* __restrict__ query,
    const float* __restrict__ Wu, const float* __restrict__ bu,
    const float* __restrict__ Wq, const float* __restrict__ bq){
    int w = blockIdx.x*8 + (threadIdx.x>>5);
    int lane = threadIdx.x&31;
    const float *x, *W, *b; float* out; int i;
    if (w < 256){ x=user;  W=Wu; b=bu; out=g_u;  i=w; }
    else        { x=query; W=Wq; b=bq; out=g_qv; i=w-256; }
    float s=0.f;
    #pragma unroll
    for (int t=0;t<24;t++){ int jj=lane+t*32; s += x[jj]*W[i*768+jj]; }
    s = wreduce(s);
    if (!lane) out[i] = s + b[i];
}

// ---- prep 2: k, v ----
__global__ void __launch_bounds__(256) prep_kv(
    const float* __restrict__ ipw, const float* __restrict__ ipb){
    int w = blockIdx.x*8 + (threadIdx.x>>5);   // 0..1023
    int lane = threadIdx.x&31;
    int i = w & 255;
    int which = w >> 8;
    int c = which & 1;
    int kv = which >> 1;
    const float* ctx = c ? g_qv : g_u;
    int row = 256 + kv*256 + i;
    float s=0.f;
    #pragma unroll
    for (int t=0;t<8;t++){ int jj=lane+t*32; s += ctx[jj]*ipw[row*256+jj]; }
    s = wreduce(s);
    if (!lane){
        float val = s + ipb[row];
        if (kv) g_v[c*256+i] = val; else g_k[c*256+i] = val;
    }
}

// ---- prep 3 (merged): blocks 0..416 = W_s/b_s/base/c ; blocks 417..440 = Wl pack
__global__ void __launch_bounds__(256) prep_sb(
    const float* __restrict__ ipw, const float* __restrict__ ipb,
    const float* __restrict__ opw, const float* __restrict__ opb,
    const float* __restrict__ Wl){
    if (blockIdx.x >= 417){
        // fp16-packed, fragment-swizzled weights
        int kt = blockIdx.x - 417;    // 0..23
        int n  = threadIdx.x;         // 0..255
        int qq = n & 7, ntg = n >> 3;
        uint32_t* dst = g_Wh + kt*B_U32;
        #pragma unroll
        for (int kp=0; kp<16; kp++){
            float lo = Wl[n*768 + kt*32 + kp*2];
            float hi = Wl[n*768 + kt*32 + kp*2 + 1];
            int s = (qq&1)*4 + (kp&3);
            int chunk = (ntg>>2) ^ s;
            dst[(kp*8+qq)*32 + chunk*4 + (ntg&3)] = packh2(lo, hi);
        }
        return;
    }
    int w = blockIdx.x*8 + (threadIdx.x>>5);
    int lane = threadIdx.x&31;
    float s=0.f;
    if (w < 256){
        int i=w;
        #pragma unroll
        for (int t=0;t<8;t++){ int jj=lane+t*32; s += g_v[256+jj]*opw[i*256+jj]; }
        s = wreduce(s);
        if (!lane) g_base[i] = s + opb[i];
    } else if (w < 1280){
        int o=w-256, h=o>>8, i=o&255;
        #pragma unroll
        for (int t=0;t<2;t++){ int d=lane+t*32; int jj=h*64+d;
            s += (g_v[jj]-g_v[256+jj])*opw[i*256+jj]; }
        s = wreduce(s);
        if (!lane) g_cc[h*256+i] = s;
    } else if (w < 3328){
        int o=w-1280, r=o>>8, i=o&255, h=r>>1, kidx=r&1;
        #pragma unroll
        for (int t=0;t<2;t++){ int d=lane+t*32;
            s += g_k[kidx*256+h*64+d]*ipw[(h*64+d)*256+i]; }
        s = wreduce(s);
        if (!lane) g_Ws[r*256+i] = 0.125f*s;
    } else if (w < 3336){
        int r=w-3328, h=r>>1, kidx=r&1;
        #pragma unroll
        for (int t=0;t<2;t++){ int d=lane+t*32;
            s += ipb[h*64+d]*g_k[kidx*256+h*64+d]; }
        s = wreduce(s);
        if (!lane) g_bs[r] = 0.125f*s;
    }
}

// ---- main GEMM + fused epilogue (R7 measured-best config) ----
__global__ void __launch_bounds__(256,1) main_gemm(
    const float* __restrict__ llm, const float* __restrict__ Wo,
    const float* __restrict__ bo, const float* __restrict__ bl,
    float* __restrict__ out){
    extern __shared__ float sm[];
    const int tid = threadIdx.x, lane = tid&31, warp = tid>>5;
    const int j = lane&3, qq = lane>>2;
    const int wm = warp&1, wn = warp>>1;           // 2 x 4 warp grid
    const uint32_t smu = (uint32_t)__cvta_generic_to_shared(sm);
    float* epi = sm + EPI_F;

    auto issue = [&](int kt){
        int slot = kt % NSTAGE;
        uint32_t sb = smu + (uint32_t)(slot*STAGE_FLOATS)*4u;
        const float* Asrc = llm + (size_t)blockIdx.x*(128*768) + kt*32;
        #pragma unroll
        for (int ch=tid; ch<1024; ch+=256){
            int row = ch>>3, u = ch&7;
            cpa16(sb + (uint32_t)(row*ASTRIDE + u*4)*4u, Asrc + (size_t)row*768 + u*4);
        }
        const uint32_t* Bsrc = g_Wh + kt*B_U32;
        uint32_t bb = sb + (uint32_t)A_FLOATS*4u;
        #pragma unroll
        for (int ch=tid; ch<1024; ch+=256)
            cpa16(bb + (uint32_t)ch*16u, Bsrc + ch*4);
    };

    issue(0); cp_commit();
    issue(1); cp_commit();

    // stage epilogue constants (overlaps async loads); dWs/dbs formed inline
    {
        int i = tid;
        epi[EPI_BASE+i] = g_base[i];
        #pragma unroll
        for (int h=0;h<4;h++) epi[EPI_CC + h*256 + i] = g_cc[h*256+i];
        epi[EPI_WOA+i] = __ldg(Wo+i);
        epi[EPI_WOL+i] = __ldg(Wo+256+i);
        epi[EPI_BL +i] = __ldg(bl+i);
        #pragma unroll
        for (int h=0;h<4;h++)
            epi[EPI_DWS + h*256 + i] = g_Ws[(2*h)*256+i] - g_Ws[(2*h+1)*256+i];
        if (i<4) epi[EPI_DBS+i] = g_bs[2*i] - g_bs[2*i+1];
    }

    float acc[4][8][4];
    #pragma unroll
    for (int t=0;t<4;t++)
        #pragma unroll
        for (int nt=0;nt<8;nt++)
            #pragma unroll
            for (int c=0;c<4;c++) acc[t][nt][c]=0.f;

    const int bsw = (qq&1)*4 + j;          // B chunk swizzle key

    for (int kt=0; kt<KTILES; kt++){
        if (kt+2 < KTILES) issue(kt+2);
        cp_commit();
        cp_wait2();
        __syncthreads();

        const int slot = kt % NSTAGE;
        const float* As = sm + slot*STAGE_FLOATS;
        const uint32_t* Bs = (const uint32_t*)(As + A_FLOATS);

        #pragma unroll
        for (int ks=0; ks<2; ks++){
            // B fragments: 4 x LDS.128
            uint32_t bf[2][8];
            #pragma unroll
            for (int r=0;r<2;r++){
                const int kp = ks*8 + j + r*4;
                const uint32_t* cell = Bs + (kp*8+qq)*32;
                #pragma unroll
                for (int c=0;c<2;c++){
                    const int chunk = (wn*2 + c) ^ bsw;
                    const uint4 v = *(const uint4*)(cell + chunk*4);
                    bf[r][c*4+0]=v.x; bf[r][c*4+1]=v.y; bf[r][c*4+2]=v.z; bf[r][c*4+3]=v.w;
                }
            }
            // A fragments: 16 x LDS.64 + cvt
            uint32_t af[4][4];
            const int k0 = ks*16 + 2*j;
            #pragma unroll
            for (int t=0;t<4;t++){
                const int row = wm*64 + t*16 + qq;
                float2 p0 = *(const float2*)(As + row*ASTRIDE + k0);
                float2 p1 = *(const float2*)(As + (row+8)*ASTRIDE + k0);
                float2 p2 = *(const float2*)(As + row*ASTRIDE + k0 + 8);
                float2 p3 = *(const float2*)(As + (row+8)*ASTRIDE + k0 + 8);
                af[t][0] = packh2(p0.x, p0.y);
                af[t][1] = packh2(p1.x, p1.y);
                af[t][2] = packh2(p2.x, p2.y);
                af[t][3] = packh2(p3.x, p3.y);
            }
            #pragma unroll
            for (int t=0;t<4;t++)
                #pragma unroll
                for (int nt=0;nt<8;nt++)
                    mma_f16(acc[t][nt][0],acc[t][nt][1],acc[t][nt][2],acc[t][nt][3],
                            af[t][0],af[t][1],af[t][2],af[t][3],
                            bf[0][nt], bf[1][nt]);
        }
        __syncthreads();
    }

    // ---- epilogue phase A: per-thread partials over owned cols ----
    // score accumulated over lv = acc + bl  (absorbs dWs.bl constant)
    float pl[4][2];
    float sh[4][2][4];
    #pragma unroll
    for (int t=0;t<4;t++)
        #pragma unroll
        for (int hf=0;hf<2;hf++){
            pl[t][hf]=0.f;
            #pragma unroll
            for (int h=0;h<4;h++) sh[t][hf][h]=0.f;
        }
    #pragma unroll
    for (int nt=0;nt<8;nt++){
        #pragma unroll
        for (int cb=0;cb<2;cb++){
            const int col = wn*64 + nt*8 + 2*j + cb;
            const float blv = epi[EPI_BL+col];
            const float wol = epi[EPI_WOL+col];
            const float w0 = epi[EPI_DWS+col];
            const float w1 = epi[EPI_DWS+256+col];
            const float w2 = epi[EPI_DWS+512+col];
            const float w3 = epi[EPI_DWS+768+col];
            #pragma unroll
            for (int t=0;t<4;t++)
                #pragma unroll
                for (int hf=0;hf<2;hf++){
                    float lv = acc[t][nt][hf*2+cb] + blv;
                    pl[t][hf] += fmaxf(lv,0.f)*wol;
                    sh[t][hf][0] += w0*lv;
                    sh[t][hf][1] += w1*lv;
                    sh[t][hf][2] += w2*lv;
                    sh[t][hf][3] += w3*lv;
                }
        }
    }
    #pragma unroll
    for (int t=0;t<4;t++)
        #pragma unroll
        for (int hf=0;hf<2;hf++){
            float v4 = pl[t][hf];
            v4 += __shfl_xor_sync(0xffffffffu, v4, 1);
            v4 += __shfl_xor_sync(0xffffffffu, v4, 2);
            float vh[4];
            #pragma unroll
            for (int h=0;h<4;h++){
                float v = sh[t][hf][h];
                v += __shfl_xor_sync(0xffffffffu, v, 1);
                v += __shfl_xor_sync(0xffffffffu, v, 2);
                vh[h]=v;
            }
            if (j==0){
                int row = wm*64 + t*16 + qq + hf*8;
                float* rp = epi + EPI_RED + (row*4+wn)*5;
                rp[0]=vh[0]; rp[1]=vh[1]; rp[2]=vh[2]; rp[3]=vh[3]; rp[4]=v4;
            }
        }
    __syncthreads();

    // ---- phase B: per-row scores + sigmoid ----
    if (tid < 128){
        int row = tid;
        float s0=epi[EPI_DBS+0], s1=epi[EPI_DBS+1], s2=epi[EPI_DBS+2], s3=epi[EPI_DBS+3];
        float p=0.f;
        #pragma unroll
        for (int w=0;w<4;w++){
            float* rp = epi + EPI_RED + (row*4+w)*5;
            s0+=rp[0]; s1+=rp[1]; s2+=rp[2]; s3+=rp[3]; p+=rp[4];
        }
        epi[EPI_AW+row*4+0] = 1.f/(1.f+expf(-s0));
        epi[EPI_AW+row*4+1] = 1.f/(1.f+expf(-s1));
        epi[EPI_AW+row*4+2] = 1.f/(1.f+expf(-s2));
        epi[EPI_AW+row*4+3] = 1.f/(1.f+expf(-s3));
        epi[EPI_PL+row] = p;
    }
    __syncthreads();

    // ---- phase C: attention dot, 2 threads per row ----
    {
        int row = tid & 127, hf = tid >> 7;
        float a0=epi[EPI_AW+row*4+0], a1=epi[EPI_AW+row*4+1],
              a2=epi[EPI_AW+row*4+2], a3=epi[EPI_AW+row*4+3];
        float p2=0.f;
        #pragma unroll 8
        for (int d=hf*128; d<hf*128+128; d++){
            float att = epi[EPI_BASE+d] + a0*epi[EPI_CC+d] + a1*epi[EPI_CC+256+d]
                      + a2*epi[EPI_CC+512+d] + a3*epi[EPI_CC+768+d];
            p2 += fmaxf(att,0.f)*epi[EPI_WOA+d];
        }
        epi[EPI_RED2 + row*2 + hf] = p2;
    }
    __syncthreads();

    if (tid < 128){
        out[blockIdx.x*128 + tid] = epi[EPI_PL+tid] + epi[EPI_RED2+tid*2]
                                  + epi[EPI_RED2+tid*2+1] + __ldg(bo);
    }
}

// ---------------------------------------------------------------------------
extern "C" void kernel_launch(void* const* d_in, const int* in_sizes, int n_in,
                              void* d_out, int out_size){
    const float* user  = (const float*)d_in[0];
    const float* query = (const float*)d_in[1];
    const float* llm   = (const float*)d_in[2];
    const float* Wu    = (const float*)d_in[3];
    const float* bu    = (const float*)d_in[4];
    const float* Wq    = (const float*)d_in[5];
    const float* bq    = (const float*)d_in[6];
    const float* Wl    = (const float*)d_in[7];
    const float* bl    = (const float*)d_in[8];
    const float* ipw   = (const float*)d_in[9];
    const float* ipb   = (const float*)d_in[10];
    const float* opw   = (const float*)d_in[11];
    const float* opb   = (const float*)d_in[12];
    const float* Wo    = (const float*)d_in[13];
    const float* bo    = (const float*)d_in[14];
    float* out = (float*)d_out;

    int M = in_sizes[2] / 768;

    cudaFuncSetAttribute(main_gemm, cudaFuncAttributeMaxDynamicSharedMemorySize, SMEM_BYTES);

    prep_uq <<<64, 256>>>(user, query, Wu, bu, Wq, bq);
    prep_kv <<<128,256>>>(ipw, ipb);
    prep_sb <<<441,256>>>(ipw, ipb, opw, opb, Wl);
    main_gemm <<<M/128, 256, SMEM_BYTES>>>(llm, Wo, bo, bl, out);
}

// round 14
// speedup vs baseline: 2.6398x; 1.0153x over previous
#include <cuda_runtime.h>
#include <cstdint>
#include <math.h>

// ---------------------------------------------------------------------------
// PreferencePredictor (sm_100, mma.sync m16n8k16 fp16) — round 14
//
//   l      = llm @ Wl.T (+bl in epilogue)     [M,256]  GEMM, BM=128 BN=256
//   s_h    = dbs_h + dWs_h . (acc+bl)         -> a_h = sigmoid(s_h)
//   att    = base + sum_h a_h * c_h           [256]
//   logit  = relu(att)@Wo[:256] + relu(l)@Wo[256:] + bo
//
// vs R13 (best, 237.4us): mainloop pipeline switched to wait_group(1) +
// SINGLE __syncthreads per k-tile (R12 discipline on the measured-best
// 256-thread 2x4 warp grid). Everything else identical.
// ---------------------------------------------------------------------------

#define KTILES 24
#define ASTRIDE 40                          // floats per A row (conflict-free LDS.64)
#define A_FLOATS (128*ASTRIDE)              // 5120
#define B_U32    4096                       // 16 kpairs x 256 n half2
#define STAGE_FLOATS (A_FLOATS + B_U32)     // 9216
#define NSTAGE 3
#define EPI_F (NSTAGE*STAGE_FLOATS)         // 27648

#define EPI_BASE 0
#define EPI_CC   256
#define EPI_WOA  1280
#define EPI_WOL  1536
#define EPI_BL   1792
#define EPI_DWS  2048
#define EPI_DBS  3072
#define EPI_RED  3080                        // [128][4][5]
#define EPI_AW   5640                        // [128][4]
#define EPI_PL   6152                        // [128]
#define EPI_RED2 6280                        // [128][2]
#define EPI_TOT  6536
#define SMEM_BYTES ((EPI_F + EPI_TOT)*4)

// ---- persistent scratch ----
__device__ __align__(256) float g_u[256], g_qv[256];
__device__ __align__(256) float g_k[512], g_v[512];
__device__ __align__(256) float g_Ws[8*256], g_bs[8];
__device__ __align__(256) float g_base[256], g_cc[4*256];
__device__ __align__(256) uint32_t g_Wh[24*B_U32];  // half2-packed swizzled Wl

// ---- helpers ----
__device__ __forceinline__ uint32_t packh2(float lo, float hi){
    uint32_t r; asm("cvt.rn.f16x2.f32 %0, %1, %2;" : "=r"(r) : "f"(hi), "f"(lo)); return r;
}
__device__ __forceinline__ void cpa16(uint32_t dst, const void* src){
    asm volatile("cp.async.cg.shared.global [%0], [%1], 16;" :: "r"(dst), "l"(src));
}
__device__ __forceinline__ void cp_commit(){ asm volatile("cp.async.commit_group;" ::: "memory"); }
__device__ __forceinline__ void cp_wait1(){ asm volatile("cp.async.wait_group 1;" ::: "memory"); }

__device__ __forceinline__ void mma_f16(float&c0,float&c1,float&c2,float&c3,
                                        uint32_t a0,uint32_t a1,uint32_t a2,uint32_t a3,
                                        uint32_t b0,uint32_t b1){
    asm volatile(
        "mma.sync.aligned.m16n8k16.row.col.f32.f16.f16.f32 "
        "{%0,%1,%2,%3},{%4,%5,%6,%7},{%8,%9},{%0,%1,%2,%3};"
        : "+f"(c0),"+f"(c1),"+f"(c2),"+f"(c3)
        : "r"(a0),"r"(a1),"r"(a2),"r"(a3),"r"(b0),"r"(b1));
}
__device__ __forceinline__ float wreduce(float s){
    #pragma unroll
    for (int o=16;o;o>>=1) s += __shfl_xor_sync(0xffffffffu, s, o);
    return s;
}

// ---- prep 1: u, qv ----
__global__ void __launch_bounds__(256) prep_uq(
    const float* __restrict__ user, const float* __restrict__ query,
    const float* __restrict__ Wu, const float* __restrict__ bu,
    const float* __restrict__ Wq, const float* __restrict__ bq){
    int w = blockIdx.x*8 + (threadIdx.x>>5);
    int lane = threadIdx.x&31;
    const float *x, *W, *b; float* out; int i;
    if (w < 256){ x=user;  W=Wu; b=bu; out=g_u;  i=w; }
    else        { x=query; W=Wq; b=bq; out=g_qv; i=w-256; }
    float s=0.f;
    #pragma unroll
    for (int t=0;t<24;t++){ int jj=lane+t*32; s += x[jj]*W[i*768+jj]; }
    s = wreduce(s);
    if (!lane) out[i] = s + b[i];
}

// ---- prep 2: k, v ----
__global__ void __launch_bounds__(256) prep_kv(
    const float* __restrict__ ipw, const float* __restrict__ ipb){
    int w = blockIdx.x*8 + (threadIdx.x>>5);   // 0..1023
    int lane = threadIdx.x&31;
    int i = w & 255;
    int which = w >> 8;
    int c = which & 1;
    int kv = which >> 1;
    const float* ctx = c ? g_qv : g_u;
    int row = 256 + kv*256 + i;
    float s=0.f;
    #pragma unroll
    for (int t=0;t<8;t++){ int jj=lane+t*32; s += ctx[jj]*ipw[row*256+jj]; }
    s = wreduce(s);
    if (!lane){
        float val = s + ipb[row];
        if (kv) g_v[c*256+i] = val; else g_k[c*256+i] = val;
    }
}

// ---- prep 3 (merged): blocks 0..416 = W_s/b_s/base/c ; blocks 417..440 = Wl pack
__global__ void __launch_bounds__(256) prep_sb(
    const float* __restrict__ ipw, const float* __restrict__ ipb,
    const float* __restrict__ opw, const float* __restrict__ opb,
    const float* __restrict__ Wl){
    if (blockIdx.x >= 417){
        // fp16-packed, fragment-swizzled weights
        int kt = blockIdx.x - 417;    // 0..23
        int n  = threadIdx.x;         // 0..255
        int qq = n & 7, ntg = n >> 3;
        uint32_t* dst = g_Wh + kt*B_U32;
        #pragma unroll
        for (int kp=0; kp<16; kp++){
            float lo = Wl[n*768 + kt*32 + kp*2];
            float hi = Wl[n*768 + kt*32 + kp*2 + 1];
            int s = (qq&1)*4 + (kp&3);
            int chunk = (ntg>>2) ^ s;
            dst[(kp*8+qq)*32 + chunk*4 + (ntg&3)] = packh2(lo, hi);
        }
        return;
    }
    int w = blockIdx.x*8 + (threadIdx.x>>5);
    int lane = threadIdx.x&31;
    float s=0.f;
    if (w < 256){
        int i=w;
        #pragma unroll
        for (int t=0;t<8;t++){ int jj=lane+t*32; s += g_v[256+jj]*opw[i*256+jj]; }
        s = wreduce(s);
        if (!lane) g_base[i] = s + opb[i];
    } else if (w < 1280){
        int o=w-256, h=o>>8, i=o&255;
        #pragma unroll
        for (int t=0;t<2;t++){ int d=lane+t*32; int jj=h*64+d;
            s += (g_v[jj]-g_v[256+jj])*opw[i*256+jj]; }
        s = wreduce(s);
        if (!lane) g_cc[h*256+i] = s;
    } else if (w < 3328){
        int o=w-1280, r=o>>8, i=o&255, h=r>>1, kidx=r&1;
        #pragma unroll
        for (int t=0;t<2;t++){ int d=lane+t*32;
            s += g_k[kidx*256+h*64+d]*ipw[(h*64+d)*256+i]; }
        s = wreduce(s);
        if (!lane) g_Ws[r*256+i] = 0.125f*s;
    } else if (w < 3336){
        int r=w-3328, h=r>>1, kidx=r&1;
        #pragma unroll
        for (int t=0;t<2;t++){ int d=lane+t*32;
            s += ipb[h*64+d]*g_k[kidx*256+h*64+d]; }
        s = wreduce(s);
        if (!lane) g_bs[r] = 0.125f*s;
    }
}

// ---- main GEMM + fused epilogue (256 threads, 2x4 warp grid) ----
__global__ void __launch_bounds__(256,1) main_gemm(
    const float* __restrict__ llm, const float* __restrict__ Wo,
    const float* __restrict__ bo, const float* __restrict__ bl,
    float* __restrict__ out){
    extern __shared__ float sm[];
    const int tid = threadIdx.x, lane = tid&31, warp = tid>>5;
    const int j = lane&3, qq = lane>>2;
    const int wm = warp&1, wn = warp>>1;           // 2 x 4 warp grid
    const uint32_t smu = (uint32_t)__cvta_generic_to_shared(sm);
    float* epi = sm + EPI_F;

    auto issue = [&](int kt){
        int slot = kt % NSTAGE;
        uint32_t sb = smu + (uint32_t)(slot*STAGE_FLOATS)*4u;
        const float* Asrc = llm + (size_t)blockIdx.x*(128*768) + kt*32;
        #pragma unroll
        for (int ch=tid; ch<1024; ch+=256){
            int row = ch>>3, u = ch&7;
            cpa16(sb + (uint32_t)(row*ASTRIDE + u*4)*4u, Asrc + (size_t)row*768 + u*4);
        }
        const uint32_t* Bsrc = g_Wh + kt*B_U32;
        uint32_t bb = sb + (uint32_t)A_FLOATS*4u;
        #pragma unroll
        for (int ch=tid; ch<1024; ch+=256)
            cpa16(bb + (uint32_t)ch*16u, Bsrc + ch*4);
    };

    issue(0); cp_commit();
    issue(1); cp_commit();

    // stage epilogue constants (overlaps async loads); dWs/dbs formed inline
    {
        int i = tid;
        epi[EPI_BASE+i] = g_base[i];
        #pragma unroll
        for (int h=0;h<4;h++) epi[EPI_CC + h*256 + i] = g_cc[h*256+i];
        epi[EPI_WOA+i] = __ldg(Wo+i);
        epi[EPI_WOL+i] = __ldg(Wo+256+i);
        epi[EPI_BL +i] = __ldg(bl+i);
        #pragma unroll
        for (int h=0;h<4;h++)
            epi[EPI_DWS + h*256 + i] = g_Ws[(2*h)*256+i] - g_Ws[(2*h+1)*256+i];
        if (i<4) epi[EPI_DBS+i] = g_bs[2*i] - g_bs[2*i+1];
    }

    float acc[4][8][4];
    #pragma unroll
    for (int t=0;t<4;t++)
        #pragma unroll
        for (int nt=0;nt<8;nt++)
            #pragma unroll
            for (int c=0;c<4;c++) acc[t][nt][c]=0.f;

    const int bsw = (qq&1)*4 + j;          // B chunk swizzle key

    for (int kt=0; kt<KTILES; kt++){
        cp_wait1();              // tile kt resident (kt+1 still in flight)
        __syncthreads();         // also closes iteration kt-1's reads of slot (kt+2)%3
        if (kt+2 < KTILES) issue(kt+2);
        cp_commit();             // always commit (keeps group ledger constant)

        const int slot = kt % NSTAGE;
        const float* As = sm + slot*STAGE_FLOATS;
        const uint32_t* Bs = (const uint32_t*)(As + A_FLOATS);

        #pragma unroll
        for (int ks=0; ks<2; ks++){
            // B fragments: 4 x LDS.128
            uint32_t bf[2][8];
            #pragma unroll
            for (int r=0;r<2;r++){
                const int kp = ks*8 + j + r*4;
                const uint32_t* cell = Bs + (kp*8+qq)*32;
                #pragma unroll
                for (int c=0;c<2;c++){
                    const int chunk = (wn*2 + c) ^ bsw;
                    const uint4 v = *(const uint4*)(cell + chunk*4);
                    bf[r][c*4+0]=v.x; bf[r][c*4+1]=v.y; bf[r][c*4+2]=v.z; bf[r][c*4+3]=v.w;
                }
            }
            // A fragments: 16 x LDS.64 + cvt
            uint32_t af[4][4];
            const int k0 = ks*16 + 2*j;
            #pragma unroll
            for (int t=0;t<4;t++){
                const int row = wm*64 + t*16 + qq;
                float2 p0 = *(const float2*)(As + row*ASTRIDE + k0);
                float2 p1 = *(const float2*)(As + (row+8)*ASTRIDE + k0);
                float2 p2 = *(const float2*)(As + row*ASTRIDE + k0 + 8);
                float2 p3 = *(const float2*)(As + (row+8)*ASTRIDE + k0 + 8);
                af[t][0] = packh2(p0.x, p0.y);
                af[t][1] = packh2(p1.x, p1.y);
                af[t][2] = packh2(p2.x, p2.y);
                af[t][3] = packh2(p3.x, p3.y);
            }
            #pragma unroll
            for (int t=0;t<4;t++)
                #pragma unroll
                for (int nt=0;nt<8;nt++)
                    mma_f16(acc[t][nt][0],acc[t][nt][1],acc[t][nt][2],acc[t][nt][3],
                            af[t][0],af[t][1],af[t][2],af[t][3],
                            bf[0][nt], bf[1][nt]);
        }
    }
    __syncthreads();

    // ---- epilogue phase A: per-thread partials over owned cols ----
    // score accumulated over lv = acc + bl  (absorbs dWs.bl constant)
    float pl[4][2];
    float sh[4][2][4];
    #pragma unroll
    for (int t=0;t<4;t++)
        #pragma unroll
        for (int hf=0;hf<2;hf++){
            pl[t][hf]=0.f;
            #pragma unroll
            for (int h=0;h<4;h++) sh[t][hf][h]=0.f;
        }
    #pragma unroll
    for (int nt=0;nt<8;nt++){
        #pragma unroll
        for (int cb=0;cb<2;cb++){
            const int col = wn*64 + nt*8 + 2*j + cb;
            const float blv = epi[EPI_BL+col];
            const float wol = epi[EPI_WOL+col];
            const float w0 = epi[EPI_DWS+col];
            const float w1 = epi[EPI_DWS+256+col];
            const float w2 = epi[EPI_DWS+512+col];
            const float w3 = epi[EPI_DWS+768+col];
            #pragma unroll
            for (int t=0;t<4;t++)
                #pragma unroll
                for (int hf=0;hf<2;hf++){
                    float lv = acc[t][nt][hf*2+cb] + blv;
                    pl[t][hf] += fmaxf(lv,0.f)*wol;
                    sh[t][hf][0] += w0*lv;
                    sh[t][hf][1] += w1*lv;
                    sh[t][hf][2] += w2*lv;
                    sh[t][hf][3] += w3*lv;
                }
        }
    }
    #pragma unroll
    for (int t=0;t<4;t++)
        #pragma unroll
        for (int hf=0;hf<2;hf++){
            float v4 = pl[t][hf];
            v4 += __shfl_xor_sync(0xffffffffu, v4, 1);
            v4 += __shfl_xor_sync(0xffffffffu, v4, 2);
            float vh[4];
            #pragma unroll
            for (int h=0;h<4;h++){
                float v = sh[t][hf][h];
                v += __shfl_xor_sync(0xffffffffu, v, 1);
                v += __shfl_xor_sync(0xffffffffu, v, 2);
                vh[h]=v;
            }
            if (j==0){
                int row = wm*64 + t*16 + qq + hf*8;
                float* rp = epi + EPI_RED + (row*4+wn)*5;
                rp[0]=vh[0]; rp[1]=vh[1]; rp[2]=vh[2]; rp[3]=vh[3]; rp[4]=v4;
            }
        }
    __syncthreads();

    // ---- phase B: per-row scores + sigmoid ----
    if (tid < 128){
        int row = tid;
        float s0=epi[EPI_DBS+0], s1=epi[EPI_DBS+1], s2=epi[EPI_DBS+2], s3=epi[EPI_DBS+3];
        float p=0.f;
        #pragma unroll
        for (int w=0;w<4;w++){
            float* rp = epi + EPI_RED + (row*4+w)*5;
            s0+=rp[0]; s1+=rp[1]; s2+=rp[2]; s3+=rp[3]; p+=rp[4];
        }
        epi[EPI_AW+row*4+0] = 1.f/(1.f+expf(-s0));
        epi[EPI_AW+row*4+1] = 1.f/(1.f+expf(-s1));
        epi[EPI_AW+row*4+2] = 1.f/(1.f+expf(-s2));
        epi[EPI_AW+row*4+3] = 1.f/(1.f+expf(-s3));
        epi[EPI_PL+row] = p;
    }
    __syncthreads();

    // ---- phase C: attention dot, 2 threads per row ----
    {
        int row = tid & 127, hf = tid >> 7;
        float a0=epi[EPI_AW+row*4+0], a1=epi[EPI_AW+row*4+1],
              a2=epi[EPI_AW+row*4+2], a3=epi[EPI_AW+row*4+3];
        float p2=0.f;
        #pragma unroll 8
        for (int d=hf*128; d<hf*128+128; d++){
            float att = epi[EPI_BASE+d] + a0*epi[EPI_CC+d] + a1*epi[EPI_CC+256+d]
                      + a2*epi[EPI_CC+512+d] + a3*epi[EPI_CC+768+d];
            p2 += fmaxf(att,0.f)*epi[EPI_WOA+d];
        }
        epi[EPI_RED2 + row*2 + hf] = p2;
    }
    __syncthreads();

    if (tid < 128){
        out[blockIdx.x*128 + tid] = epi[EPI_PL+tid] + epi[EPI_RED2+tid*2]
                                  + epi[EPI_RED2+tid*2+1] + __ldg(bo);
    }
}

// ---------------------------------------------------------------------------
extern "C" void kernel_launch(void* const* d_in, const int* in_sizes, int n_in,
                              void* d_out, int out_size){
    const float* user  = (const float*)d_in[0];
    const float* query = (const float*)d_in[1];
    const float* llm   = (const float*)d_in[2];
    const float* Wu    = (const float*)d_in[3];
    const float* bu    = (const float*)d_in[4];
    const float* Wq    = (const float*)d_in[5];
    const float* bq    = (const float*)d_in[6];
    const float* Wl    = (const float*)d_in[7];
    const float* bl    = (const float*)d_in[8];
    const float* ipw   = (const float*)d_in[9];
    const float* ipb   = (const float*)d_in[10];
    const float* opw   = (const float*)d_in[11];
    const float* opb   = (const float*)d_in[12];
    const float* Wo    = (const float*)d_in[13];
    const float* bo    = (const float*)d_in[14];
    float* out = (float*)d_out;

    int M = in_sizes[2] / 768;

    cudaFuncSetAttribute(main_gemm, cudaFuncAttributeMaxDynamicSharedMemorySize, SMEM_BYTES);

    prep_uq <<<64, 256>>>(user, query, Wu, bu, Wq, bq);
    prep_kv <<<128,256>>>(ipw, ipb);
    prep_sb <<<441,256>>>(ipw, ipb, opw, opb, Wl);
    main_gemm <<<M/128, 256, SMEM_BYTES>>>(llm, Wo, bo, bl, out);
}

// round 16
// speedup vs baseline: 2.9440x; 1.1152x over previous
#include <cuda_runtime.h>
#include <cstdint>
#include <math.h>

// ---------------------------------------------------------------------------
// PreferencePredictor (sm_100, mma.sync m16n8k16 fp16) — round 16
// (resubmit of R15; R15 bench was an infra failure, kernel never ran)
//
//   l      = llm @ Wl.T (+bl in epilogue)     [M,256]  GEMM, BM=128 BN=256
//   s_h    = dbs_h + dWs_h . (acc+bl)         -> a_h = sigmoid(s_h)
//   att    = base + sum_h a_h * c_h           [256]
//   logit  = relu(att)@Wo[:256] + relu(l)@Wo[256:] + bo
//
// vs R14 (best, 233.9us): mainloop scheduling only —
//   (1) full-tile fragment preload (both ks) before any mma,
//   (2) issue(kt+2) moved after fragment loads,
//   (3) unroll-by-3 on kt so the stage slot is compile-time constant.
// ---------------------------------------------------------------------------

#define KTILES 24
#define ASTRIDE 40                          // floats per A row (conflict-free LDS.64)
#define A_FLOATS (128*ASTRIDE)              // 5120
#define B_U32    4096                       // 16 kpairs x 256 n half2
#define STAGE_FLOATS (A_FLOATS + B_U32)     // 9216
#define NSTAGE 3
#define EPI_F (NSTAGE*STAGE_FLOATS)         // 27648

#define EPI_BASE 0
#define EPI_CC   256
#define EPI_WOA  1280
#define EPI_WOL  1536
#define EPI_BL   1792
#define EPI_DWS  2048
#define EPI_DBS  3072
#define EPI_RED  3080                        // [128][4][5]
#define EPI_AW   5640                        // [128][4]
#define EPI_PL   6152                        // [128]
#define EPI_RED2 6280                        // [128][2]
#define EPI_TOT  6536
#define SMEM_BYTES ((EPI_F + EPI_TOT)*4)

// ---- persistent scratch ----
__device__ __align__(256) float g_u[256], g_qv[256];
__device__ __align__(256) float g_k[512], g_v[512];
__device__ __align__(256) float g_Ws[8*256], g_bs[8];
__device__ __align__(256) float g_base[256], g_cc[4*256];
__device__ __align__(256) uint32_t g_Wh[24*B_U32];  // half2-packed swizzled Wl

// ---- helpers ----
__device__ __forceinline__ uint32_t packh2(float lo, float hi){
    uint32_t r; asm("cvt.rn.f16x2.f32 %0, %1, %2;" : "=r"(r) : "f"(hi), "f"(lo)); return r;
}
__device__ __forceinline__ void cpa16(uint32_t dst, const void* src){
    asm volatile("cp.async.cg.shared.global [%0], [%1], 16;" :: "r"(dst), "l"(src));
}
__device__ __forceinline__ void cp_commit(){ asm volatile("cp.async.commit_group;" ::: "memory"); }
__device__ __forceinline__ void cp_wait1(){ asm volatile("cp.async.wait_group 1;" ::: "memory"); }

__device__ __forceinline__ void mma_f16(float&c0,float&c1,float&c2,float&c3,
                                        uint32_t a0,uint32_t a1,uint32_t a2,uint32_t a3,
                                        uint32_t b0,uint32_t b1){
    asm volatile(
        "mma.sync.aligned.m16n8k16.row.col.f32.f16.f16.f32 "
        "{%0,%1,%2,%3},{%4,%5,%6,%7},{%8,%9},{%0,%1,%2,%3};"
        : "+f"(c0),"+f"(c1),"+f"(c2),"+f"(c3)
        : "r"(a0),"r"(a1),"r"(a2),"r"(a3),"r"(b0),"r"(b1));
}
__device__ __forceinline__ float wreduce(float s){
    #pragma unroll
    for (int o=16;o;o>>=1) s += __shfl_xor_sync(0xffffffffu, s, o);
    return s;
}

// ---- prep 1: u, qv ----
__global__ void __launch_bounds__(256) prep_uq(
    const float* __restrict__ user, const float* __restrict__ query,
    const float* __restrict__ Wu, const float* __restrict__ bu,
    const float* __restrict__ Wq, const float* __restrict__ bq){
    int w = blockIdx.x*8 + (threadIdx.x>>5);
    int lane = threadIdx.x&31;
    const float *x, *W, *b; float* out; int i;
    if (w < 256){ x=user;  W=Wu; b=bu; out=g_u;  i=w; }
    else        { x=query; W=Wq; b=bq; out=g_qv; i=w-256; }
    float s=0.f;
    #pragma unroll
    for (int t=0;t<24;t++){ int jj=lane+t*32; s += x[jj]*W[i*768+jj]; }
    s = wreduce(s);
    if (!lane) out[i] = s + b[i];
}

// ---- prep 2: k, v ----
__global__ void __launch_bounds__(256) prep_kv(
    const float* __restrict__ ipw, const float* __restrict__ ipb){
    int w = blockIdx.x*8 + (threadIdx.x>>5);   // 0..1023
    int lane = threadIdx.x&31;
    int i = w & 255;
    int which = w >> 8;
    int c = which & 1;
    int kv = which >> 1;
    const float* ctx = c ? g_qv : g_u;
    int row = 256 + kv*256 + i;
    float s=0.f;
    #pragma unroll
    for (int t=0;t<8;t++){ int jj=lane+t*32; s += ctx[jj]*ipw[row*256+jj]; }
    s = wreduce(s);
    if (!lane){
        float val = s + ipb[row];
        if (kv) g_v[c*256+i] = val; else g_k[c*256+i] = val;
    }
}

// ---- prep 3 (merged): blocks 0..416 = W_s/b_s/base/c ; blocks 417..440 = Wl pack
__global__ void __launch_bounds__(256) prep_sb(
    const float* __restrict__ ipw, const float* __restrict__ ipb,
    const float* __restrict__ opw, const float* __restrict__ opb,
    const float* __restrict__ Wl){
    if (blockIdx.x >= 417){
        // fp16-packed, fragment-swizzled weights
        int kt = blockIdx.x - 417;    // 0..23
        int n  = threadIdx.x;         // 0..255
        int qq = n & 7, ntg = n >> 3;
        uint32_t* dst = g_Wh + kt*B_U32;
        #pragma unroll
        for (int kp=0; kp<16; kp++){
            float lo = Wl[n*768 + kt*32 + kp*2];
            float hi = Wl[n*768 + kt*32 + kp*2 + 1];
            int s = (qq&1)*4 + (kp&3);
            int chunk = (ntg>>2) ^ s;
            dst[(kp*8+qq)*32 + chunk*4 + (ntg&3)] = packh2(lo, hi);
        }
        return;
    }
    int w = blockIdx.x*8 + (threadIdx.x>>5);
    int lane = threadIdx.x&31;
    float s=0.f;
    if (w < 256){
        int i=w;
        #pragma unroll
        for (int t=0;t<8;t++){ int jj=lane+t*32; s += g_v[256+jj]*opw[i*256+jj]; }
        s = wreduce(s);
        if (!lane) g_base[i] = s + opb[i];
    } else if (w < 1280){
        int o=w-256, h=o>>8, i=o&255;
        #pragma unroll
        for (int t=0;t<2;t++){ int d=lane+t*32; int jj=h*64+d;
            s += (g_v[jj]-g_v[256+jj])*opw[i*256+jj]; }
        s = wreduce(s);
        if (!lane) g_cc[h*256+i] = s;
    } else if (w < 3328){
        int o=w-1280, r=o>>8, i=o&255, h=r>>1, kidx=r&1;
        #pragma unroll
        for (int t=0;t<2;t++){ int d=lane+t*32;
            s += g_k[kidx*256+h*64+d]*ipw[(h*64+d)*256+i]; }
        s = wreduce(s);
        if (!lane) g_Ws[r*256+i] = 0.125f*s;
    } else if (w < 3336){
        int r=w-3328, h=r>>1, kidx=r&1;
        #pragma unroll
        for (int t=0;t<2;t++){ int d=lane+t*32;
            s += ipb[h*64+d]*g_k[kidx*256+h*64+d]; }
        s = wreduce(s);
        if (!lane) g_bs[r] = 0.125f*s;
    }
}

// ---- main GEMM + fused epilogue (256 threads, 2x4 warp grid) ----
__global__ void __launch_bounds__(256,1) main_gemm(
    const float* __restrict__ llm, const float* __restrict__ Wo,
    const float* __restrict__ bo, const float* __restrict__ bl,
    float* __restrict__ out){
    extern __shared__ float sm[];
    const int tid = threadIdx.x, lane = tid&31, warp = tid>>5;
    const int j = lane&3, qq = lane>>2;
    const int wm = warp&1, wn = warp>>1;           // 2 x 4 warp grid
    const uint32_t smu = (uint32_t)__cvta_generic_to_shared(sm);
    float* epi = sm + EPI_F;

    auto issue = [&](int kt){
        int slot = kt % NSTAGE;
        uint32_t sb = smu + (uint32_t)(slot*STAGE_FLOATS)*4u;
        const float* Asrc = llm + (size_t)blockIdx.x*(128*768) + kt*32;
        #pragma unroll
        for (int ch=tid; ch<1024; ch+=256){
            int row = ch>>3, u = ch&7;
            cpa16(sb + (uint32_t)(row*ASTRIDE + u*4)*4u, Asrc + (size_t)row*768 + u*4);
        }
        const uint32_t* Bsrc = g_Wh + kt*B_U32;
        uint32_t bb = sb + (uint32_t)A_FLOATS*4u;
        #pragma unroll
        for (int ch=tid; ch<1024; ch+=256)
            cpa16(bb + (uint32_t)ch*16u, Bsrc + ch*4);
    };

    issue(0); cp_commit();
    issue(1); cp_commit();

    // stage epilogue constants (overlaps async loads); dWs/dbs formed inline
    {
        int i = tid;
        epi[EPI_BASE+i] = g_base[i];
        #pragma unroll
        for (int h=0;h<4;h++) epi[EPI_CC + h*256 + i] = g_cc[h*256+i];
        epi[EPI_WOA+i] = __ldg(Wo+i);
        epi[EPI_WOL+i] = __ldg(Wo+256+i);
        epi[EPI_BL +i] = __ldg(bl+i);
        #pragma unroll
        for (int h=0;h<4;h++)
            epi[EPI_DWS + h*256 + i] = g_Ws[(2*h)*256+i] - g_Ws[(2*h+1)*256+i];
        if (i<4) epi[EPI_DBS+i] = g_bs[2*i] - g_bs[2*i+1];
    }

    float acc[4][8][4];
    #pragma unroll
    for (int t=0;t<4;t++)
        #pragma unroll
        for (int nt=0;nt<8;nt++)
            #pragma unroll
            for (int c=0;c<4;c++) acc[t][nt][c]=0.f;

    const int bsw = (qq&1)*4 + j;          // B chunk swizzle key

    #pragma unroll 3
    for (int kt=0; kt<KTILES; kt++){
        cp_wait1();              // tile kt resident (kt+1 still in flight)
        __syncthreads();         // also closes iteration kt-1's reads of slot (kt+2)%3

        const int slot = kt % NSTAGE;   // compile-time under unroll-by-3
        const float* As = sm + slot*STAGE_FLOATS;
        const uint32_t* Bs = (const uint32_t*)(As + A_FLOATS);

        // ---- full-tile fragment preload (both ks) ----
        uint32_t bf[2][2][8];
        uint32_t af[2][4][4];
        #pragma unroll
        for (int ks=0; ks<2; ks++){
            #pragma unroll
            for (int r=0;r<2;r++){
                const int kp = ks*8 + j + r*4;
                const uint32_t* cell = Bs + (kp*8+qq)*32;
                #pragma unroll
                for (int c=0;c<2;c++){
                    const int chunk = (wn*2 + c) ^ bsw;
                    const uint4 v = *(const uint4*)(cell + chunk*4);
                    bf[ks][r][c*4+0]=v.x; bf[ks][r][c*4+1]=v.y;
                    bf[ks][r][c*4+2]=v.z; bf[ks][r][c*4+3]=v.w;
                }
            }
            const int k0 = ks*16 + 2*j;
            #pragma unroll
            for (int t=0;t<4;t++){
                const int row = wm*64 + t*16 + qq;
                float2 p0 = *(const float2*)(As + row*ASTRIDE + k0);
                float2 p1 = *(const float2*)(As + (row+8)*ASTRIDE + k0);
                float2 p2 = *(const float2*)(As + row*ASTRIDE + k0 + 8);
                float2 p3 = *(const float2*)(As + (row+8)*ASTRIDE + k0 + 8);
                af[ks][t][0] = packh2(p0.x, p0.y);
                af[ks][t][1] = packh2(p1.x, p1.y);
                af[ks][t][2] = packh2(p2.x, p2.y);
                af[ks][t][3] = packh2(p3.x, p3.y);
            }
        }

        // prefetch next-next tile AFTER frag loads (latency still covered)
        if (kt+2 < KTILES) issue(kt+2);
        cp_commit();             // always commit (keeps group ledger constant)

        // ---- 128 back-to-back mma ----
        #pragma unroll
        for (int ks=0; ks<2; ks++)
            #pragma unroll
            for (int t=0;t<4;t++)
                #pragma unroll
                for (int nt=0;nt<8;nt++)
                    mma_f16(acc[t][nt][0],acc[t][nt][1],acc[t][nt][2],acc[t][nt][3],
                            af[ks][t][0],af[ks][t][1],af[ks][t][2],af[ks][t][3],
                            bf[ks][0][nt], bf[ks][1][nt]);
    }
    __syncthreads();

    // ---- epilogue phase A: per-thread partials over owned cols ----
    // score accumulated over lv = acc + bl  (absorbs dWs.bl constant)
    float pl[4][2];
    float sh[4][2][4];
    #pragma unroll
    for (int t=0;t<4;t++)
        #pragma unroll
        for (int hf=0;hf<2;hf++){
            pl[t][hf]=0.f;
            #pragma unroll
            for (int h=0;h<4;h++) sh[t][hf][h]=0.f;
        }
    #pragma unroll
    for (int nt=0;nt<8;nt++){
        #pragma unroll
        for (int cb=0;cb<2;cb++){
            const int col = wn*64 + nt*8 + 2*j + cb;
            const float blv = epi[EPI_BL+col];
            const float wol = epi[EPI_WOL+col];
            const float w0 = epi[EPI_DWS+col];
            const float w1 = epi[EPI_DWS+256+col];
            const float w2 = epi[EPI_DWS+512+col];
            const float w3 = epi[EPI_DWS+768+col];
            #pragma unroll
            for (int t=0;t<4;t++)
                #pragma unroll
                for (int hf=0;hf<2;hf++){
                    float lv = acc[t][nt][hf*2+cb] + blv;
                    pl[t][hf] += fmaxf(lv,0.f)*wol;
                    sh[t][hf][0] += w0*lv;
                    sh[t][hf][1] += w1*lv;
                    sh[t][hf][2] += w2*lv;
                    sh[t][hf][3] += w3*lv;
                }
        }
    }
    #pragma unroll
    for (int t=0;t<4;t++)
        #pragma unroll
        for (int hf=0;hf<2;hf++){
            float v4 = pl[t][hf];
            v4 += __shfl_xor_sync(0xffffffffu, v4, 1);
            v4 += __shfl_xor_sync(0xffffffffu, v4, 2);
            float vh[4];
            #pragma unroll
            for (int h=0;h<4;h++){
                float v = sh[t][hf][h];
                v += __shfl_xor_sync(0xffffffffu, v, 1);
                v += __shfl_xor_sync(0xffffffffu, v, 2);
                vh[h]=v;
            }
            if (j==0){
                int row = wm*64 + t*16 + qq + hf*8;
                float* rp = epi + EPI_RED + (row*4+wn)*5;
                rp[0]=vh[0]; rp[1]=vh[1]; rp[2]=vh[2]; rp[3]=vh[3]; rp[4]=v4;
            }
        }
    __syncthreads();

    // ---- phase B: per-row scores + sigmoid ----
    if (tid < 128){
        int row = tid;
        float s0=epi[EPI_DBS+0], s1=epi[EPI_DBS+1], s2=epi[EPI_DBS+2], s3=epi[EPI_DBS+3];
        float p=0.f;
        #pragma unroll
        for (int w=0;w<4;w++){
            float* rp = epi + EPI_RED + (row*4+w)*5;
            s0+=rp[0]; s1+=rp[1]; s2+=rp[2]; s3+=rp[3]; p+=rp[4];
        }
        epi[EPI_AW+row*4+0] = 1.f/(1.f+expf(-s0));
        epi[EPI_AW+row*4+1] = 1.f/(1.f+expf(-s1));
        epi[EPI_AW+row*4+2] = 1.f/(1.f+expf(-s2));
        epi[EPI_AW+row*4+3] = 1.f/(1.f+expf(-s3));
        epi[EPI_PL+row] = p;
    }
    __syncthreads();

    // ---- phase C: attention dot, 2 threads per row ----
    {
        int row = tid & 127, hf = tid >> 7;
        float a0=epi[EPI_AW+row*4+0], a1=epi[EPI_AW+row*4+1],
              a2=epi[EPI_AW+row*4+2], a3=epi[EPI_AW+row*4+3];
        float p2=0.f;
        #pragma unroll 8
        for (int d=hf*128; d<hf*128+128; d++){
            float att = epi[EPI_BASE+d] + a0*epi[EPI_CC+d] + a1*epi[EPI_CC+256+d]
                      + a2*epi[EPI_CC+512+d] + a3*epi[EPI_CC+768+d];
            p2 += fmaxf(att,0.f)*epi[EPI_WOA+d];
        }
        epi[EPI_RED2 + row*2 + hf] = p2;
    }
    __syncthreads();

    if (tid < 128){
        out[blockIdx.x*128 + tid] = epi[EPI_PL+tid] + epi[EPI_RED2+tid*2]
                                  + epi[EPI_RED2+tid*2+1] + __ldg(bo);
    }
}

// ---------------------------------------------------------------------------
extern "C" void kernel_launch(void* const* d_in, const int* in_sizes, int n_in,
                              void* d_out, int out_size){
    const float* user  = (const float*)d_in[0];
    const float* query = (const float*)d_in[1];
    const float* llm   = (const float*)d_in[2];
    const float* Wu    = (const float*)d_in[3];
    const float* bu    = (const float*)d_in[4];
    const float* Wq    = (const float*)d_in[5];
    const float* bq    = (const float*)d_in[6];
    const float* Wl    = (const float*)d_in[7];
    const float* bl    = (const float*)d_in[8];
    const float* ipw   = (const float*)d_in[9];
    const float* ipb   = (const float*)d_in[10];
    const float* opw   = (const float*)d_in[11];
    const float* opb   = (const float*)d_in[12];
    const float* Wo    = (const float*)d_in[13];
    const float* bo    = (const float*)d_in[14];
    float* out = (float*)d_out;

    int M = in_sizes[2] / 768;

    cudaFuncSetAttribute(main_gemm, cudaFuncAttributeMaxDynamicSharedMemorySize, SMEM_BYTES);

    prep_uq <<<64, 256>>>(user, query, Wu, bu, Wq, bq);
    prep_kv <<<128,256>>>(ipw, ipb);
    prep_sb <<<441,256>>>(ipw, ipb, opw, opb, Wl);
    main_gemm <<<M/128, 256, SMEM_BYTES>>>(llm, Wo, bo, bl, out);
}